// round 1
// baseline (speedup 1.0000x reference)
#include <cuda_runtime.h>
#include <cstdint>

// ---------------------------------------------------------------------------
// LinearAttention: y = LinAttn(x) with feature-map softmax, then out-proj.
// Pipeline (all fp32 this round; tensor-core port comes later):
//   1. g_q/g_k/g_v = x @ W{q,k,v} + b      (SGEMM, 128x128x16 tiles)
//   2. softmax over head dim (64) on q, k  (1 warp per segment)
//   3. per (b,h): ctx[64][64] = k^T v ; ksum[64] = sum_t k   (T-split + atomics)
//   4. y[t,e] = (q[t,:] @ ctx[:,e]) * (1/(q.ksum)) + q[t,e]
//   5. out = y @ Wp + bp                    (SGEMM)
// ---------------------------------------------------------------------------

constexpr int Bn   = 4;
constexpr int Tn   = 4096;
constexpr int Mtot = Bn * Tn;       // 16384
constexpr int Cn   = 1024;
constexpr int Hn   = 16;
constexpr int Dn   = 64;
constexpr int BHn  = Bn * Hn;       // 64

// Scratch (device globals: allocation-free per harness rules)
__device__ float g_q[(size_t)Mtot * Cn];
__device__ float g_k[(size_t)Mtot * Cn];
__device__ float g_v[(size_t)Mtot * Cn];
__device__ float g_y[(size_t)Mtot * Cn];
__device__ float g_ctx[BHn * Dn * Dn];   // [bh][d][e]
__device__ float g_ksum[BHn * Dn];       // [bh][d]

// ---------------------------------------------------------------------------
// SGEMM + bias.  C[M,N] = A[M,K] @ W[K,N] + bias[N]
// mode 0/1/2: A = x (param), C = g_q/g_k/g_v
// mode 3    : A = g_y,       C = out (param)
// BM=BN=128, BK=16, 256 threads, 8x8 per-thread microtile.
// ---------------------------------------------------------------------------
__global__ __launch_bounds__(256)
void gemm_bias(const float* __restrict__ Aparam,
               const float* __restrict__ W,
               const float* __restrict__ bias,
               float* __restrict__ Cparam,
               int mode)
{
    constexpr int BM = 128, BN = 128, BK = 16, TM = 8, TN = 8;
    constexpr int K = Cn, N = Cn;

    const float* A;
    float* Cm;
    if (mode == 0)      { A = Aparam; Cm = g_q; }
    else if (mode == 1) { A = Aparam; Cm = g_k; }
    else if (mode == 2) { A = Aparam; Cm = g_v; }
    else                { A = g_y;    Cm = Cparam; }

    __shared__ float As[BK][BM];
    __shared__ float Bs[BK][BN];

    const int bx = blockIdx.x;           // N tile (0..7)
    const int by = blockIdx.y;           // M tile (0..127)
    const int tid = threadIdx.x;
    const int tx = tid % 16;
    const int ty = tid / 16;

    const float* Ap = A + (size_t)by * BM * K;
    const float* Wp = W + (size_t)bx * BN;

    // Loader mapping
    const int aRow = tid / 4;            // 0..63
    const int aCol = (tid % 4) * 4;      // 0,4,8,12
    const int bRow = tid / 32;           // 0..7
    const int bCol = (tid % 32) * 4;     // 0..124

    float acc[TM][TN];
#pragma unroll
    for (int i = 0; i < TM; i++)
#pragma unroll
        for (int j = 0; j < TN; j++) acc[i][j] = 0.f;

    for (int k0 = 0; k0 < K; k0 += BK) {
#pragma unroll
        for (int p = 0; p < 2; p++) {
            float4 a4 = *(const float4*)(Ap + (size_t)(aRow + p * 64) * K + k0 + aCol);
            As[aCol + 0][aRow + p * 64] = a4.x;
            As[aCol + 1][aRow + p * 64] = a4.y;
            As[aCol + 2][aRow + p * 64] = a4.z;
            As[aCol + 3][aRow + p * 64] = a4.w;
        }
#pragma unroll
        for (int p = 0; p < 2; p++) {
            *(float4*)(&Bs[bRow + p * 8][bCol]) =
                *(const float4*)(Wp + (size_t)(k0 + bRow + p * 8) * N + bCol);
        }
        __syncthreads();

#pragma unroll
        for (int kk = 0; kk < BK; kk++) {
            float a[TM], b[TN];
#pragma unroll
            for (int i = 0; i < TM; i++) a[i] = As[kk][ty * TM + i];
#pragma unroll
            for (int j = 0; j < TN; j++) b[j] = Bs[kk][tx * TN + j];
#pragma unroll
            for (int i = 0; i < TM; i++)
#pragma unroll
                for (int j = 0; j < TN; j++)
                    acc[i][j] += a[i] * b[j];
        }
        __syncthreads();
    }

#pragma unroll
    for (int i = 0; i < TM; i++) {
        const int row = by * BM + ty * TM + i;
#pragma unroll
        for (int j = 0; j < TN; j += 4) {
            const int col = bx * BN + tx * TN + j;
            float4 o;
            o.x = acc[i][j + 0] + bias[col + 0];
            o.y = acc[i][j + 1] + bias[col + 1];
            o.z = acc[i][j + 2] + bias[col + 2];
            o.w = acc[i][j + 3] + bias[col + 3];
            *(float4*)(Cm + (size_t)row * N + col) = o;
        }
    }
}

// ---------------------------------------------------------------------------
// Softmax over contiguous 64-element segments, in place, over g_q then g_k.
// Segment w: first NSEG in g_q, next NSEG in g_k.  1 warp per segment.
// ---------------------------------------------------------------------------
__global__ __launch_bounds__(256)
void softmax64()
{
    constexpr int NSEG = Mtot * Hn;  // 262144 per tensor
    const int w = (blockIdx.x * blockDim.x + threadIdx.x) >> 5;
    const int lane = threadIdx.x & 31;
    if (w >= 2 * NSEG) return;
    float* s = (w < NSEG) ? (g_q + (size_t)w * 64)
                          : (g_k + (size_t)(w - NSEG) * 64);
    float v0 = s[lane], v1 = s[lane + 32];
    float m = fmaxf(v0, v1);
#pragma unroll
    for (int o = 16; o; o >>= 1) m = fmaxf(m, __shfl_xor_sync(0xFFFFFFFFu, m, o));
    v0 = __expf(v0 - m);
    v1 = __expf(v1 - m);
    float sum = v0 + v1;
#pragma unroll
    for (int o = 16; o; o >>= 1) sum += __shfl_xor_sync(0xFFFFFFFFu, sum, o);
    const float inv = 1.0f / sum;
    s[lane] = v0 * inv;
    s[lane + 32] = v1 * inv;
}

// ---------------------------------------------------------------------------
// Zero ctx + ksum accumulators (required every invocation).
// ---------------------------------------------------------------------------
__global__ void zero_ctx()
{
    const int i = blockIdx.x * blockDim.x + threadIdx.x;
    if (i < BHn * Dn * Dn) g_ctx[i] = 0.f;
    if (i < BHn * Dn) g_ksum[i] = 0.f;
}

// ---------------------------------------------------------------------------
// Per (b,h): accumulate ctx[d][e] = sum_t k[t,d] v[t,e] and ksum[d].
// Grid: (BH=64, TSPLIT=8).  256 threads; each thread owns a 4x4 subtile.
// ---------------------------------------------------------------------------
constexpr int TSPLIT = 8;
__global__ __launch_bounds__(256)
void ctx_kernel()
{
    const int bh = blockIdx.x;
    const int b = bh / Hn, h = bh % Hn;
    const int t0 = blockIdx.y * (Tn / TSPLIT);
    const int tid = threadIdx.x;

    __shared__ float ks[32][64];
    __shared__ float vs[32][64];

    const int dbase = (tid / 16) * 4;
    const int ebase = (tid % 16) * 4;

    float acc[4][4];
#pragma unroll
    for (int i = 0; i < 4; i++)
#pragma unroll
        for (int j = 0; j < 4; j++) acc[i][j] = 0.f;
    float ksumAcc = 0.f;

    const size_t rowbase = (size_t)b * Tn * Cn + (size_t)h * Dn;

    const int lt = tid / 8;            // token within chunk 0..31
    const int ld = (tid % 8) * 8;      // d 0,8,..,56

    for (int tc = 0; tc < Tn / TSPLIT; tc += 32) {
        const size_t off = rowbase + (size_t)(t0 + tc + lt) * Cn + ld;
        float4 k0 = *(const float4*)(g_k + off);
        float4 k1 = *(const float4*)(g_k + off + 4);
        float4 v0 = *(const float4*)(g_v + off);
        float4 v1 = *(const float4*)(g_v + off + 4);
        *(float4*)&ks[lt][ld] = k0;
        *(float4*)&ks[lt][ld + 4] = k1;
        *(float4*)&vs[lt][ld] = v0;
        *(float4*)&vs[lt][ld + 4] = v1;
        __syncthreads();

#pragma unroll 8
        for (int t = 0; t < 32; t++) {
            float kr[4], vr[4];
#pragma unroll
            for (int i = 0; i < 4; i++) kr[i] = ks[t][dbase + i];
#pragma unroll
            for (int j = 0; j < 4; j++) vr[j] = vs[t][ebase + j];
#pragma unroll
            for (int i = 0; i < 4; i++)
#pragma unroll
                for (int j = 0; j < 4; j++)
                    acc[i][j] += kr[i] * vr[j];
        }
        if (tid < 64) {
#pragma unroll 8
            for (int t = 0; t < 32; t++) ksumAcc += ks[t][tid];
        }
        __syncthreads();
    }

#pragma unroll
    for (int i = 0; i < 4; i++)
#pragma unroll
        for (int j = 0; j < 4; j++)
            atomicAdd(&g_ctx[bh * Dn * Dn + (dbase + i) * Dn + ebase + j], acc[i][j]);
    if (tid < 64) atomicAdd(&g_ksum[bh * Dn + tid], ksumAcc);
}

// ---------------------------------------------------------------------------
// y[t,e] = (sum_d q[t,d] ctx[d][e]) * Dinv + q[t,e],  Dinv = 1/(q . ksum)
// Grid: (BH=64, 64 token-chunks of 64).  256 threads = 8 warps, 1 warp/token.
// ---------------------------------------------------------------------------
__global__ __launch_bounds__(256)
void y_kernel()
{
    const int bh = blockIdx.x;
    const int b = bh / Hn, h = bh % Hn;
    const int tid = threadIdx.x;
    const int w = tid >> 5, lane = tid & 31;

    __shared__ float ctx_s[64][65];
    __shared__ float ksum_s[64];
    __shared__ float qrow[8][64];

    for (int i = tid; i < Dn * Dn; i += 256)
        ctx_s[i / 64][i % 64] = g_ctx[bh * Dn * Dn + i];
    if (tid < 64) ksum_s[tid] = g_ksum[bh * Dn + tid];
    __syncthreads();

    const size_t rowbase = (size_t)b * Tn * Cn + (size_t)h * Dn;

    for (int t = blockIdx.y * 64 + w; t < blockIdx.y * 64 + 64; t += 8) {
        const float* qp = g_q + rowbase + (size_t)t * Cn;
        const float q0 = qp[lane], q1 = qp[lane + 32];
        qrow[w][lane] = q0;
        qrow[w][lane + 32] = q1;
        __syncwarp();

        float s = q0 * ksum_s[lane] + q1 * ksum_s[lane + 32];
#pragma unroll
        for (int o = 16; o; o >>= 1) s += __shfl_xor_sync(0xFFFFFFFFu, s, o);
        const float dinv = 1.0f / s;

        float a0 = 0.f, a1 = 0.f;
#pragma unroll
        for (int d = 0; d < 64; d++) {
            const float qd = qrow[w][d];
            a0 += qd * ctx_s[d][lane];
            a1 += qd * ctx_s[d][lane + 32];
        }
        float* yp = g_y + rowbase + (size_t)t * Cn;
        yp[lane] = a0 * dinv + q0;
        yp[lane + 32] = a1 * dinv + q1;
        __syncwarp();
    }
}

// ---------------------------------------------------------------------------
extern "C" void kernel_launch(void* const* d_in, const int* in_sizes, int n_in,
                              void* d_out, int out_size)
{
    const float* x  = (const float*)d_in[0];
    const float* Wq = (const float*)d_in[1];
    const float* bq = (const float*)d_in[2];
    const float* Wk = (const float*)d_in[3];
    const float* bk = (const float*)d_in[4];
    const float* Wv = (const float*)d_in[5];
    const float* bv = (const float*)d_in[6];
    const float* Wp = (const float*)d_in[7];
    const float* bp = (const float*)d_in[8];
    float* out = (float*)d_out;

    const dim3 gGemm(Cn / 128, Mtot / 128);  // (8, 128)

    gemm_bias<<<gGemm, 256>>>(x, Wq, bq, nullptr, 0);
    gemm_bias<<<gGemm, 256>>>(x, Wk, bk, nullptr, 1);
    gemm_bias<<<gGemm, 256>>>(x, Wv, bv, nullptr, 2);

    // 2 * 262144 segments, 8 warps/block
    softmax64<<<(2 * Mtot * Hn) / 8 / 1, 256>>>();  // wait: grid below
    // (grid computed explicitly:)
    // NOTE: the launch above uses 2*Mtot*Hn/8 blocks = 65536.

    zero_ctx<<<(BHn * Dn * Dn + 255) / 256, 256>>>();
    ctx_kernel<<<dim3(BHn, TSPLIT), 256>>>();
    y_kernel<<<dim3(BHn, Tn / 64), 256>>>();

    gemm_bias<<<gGemm, 256>>>(nullptr, Wp, bp, out, 3);
}

// round 4
// speedup vs baseline: 2.5513x; 2.5513x over previous
#include <cuda_runtime.h>
#include <cstdint>

// ===========================================================================
// LinearAttention — Round 4: tf32 mma.sync GEMMs (compute_100-safe).
// Identical to Round 3 design; fixes the mode-3 launch signature bug.
// Pipeline:
//   1. q/k/v = x @ W + b      (tf32 mma.sync, 128x128x16 tiles, cp.async)
//   2. softmax over head dim (64) on q, k
//   3. ctx = k^T v per (b,h); ksum
//   4. y = (q @ ctx) * Dinv + q
//   5. out = y @ Wp + bp
// ===========================================================================

constexpr int Bn   = 4;
constexpr int Tn   = 4096;
constexpr int Mtot = Bn * Tn;       // 16384
constexpr int Cn   = 1024;
constexpr int Hn   = 16;
constexpr int Dn   = 64;
constexpr int BHn  = Bn * Hn;       // 64

__device__ float g_q[(size_t)Mtot * Cn];
__device__ float g_k[(size_t)Mtot * Cn];
__device__ float g_v[(size_t)Mtot * Cn];
__device__ float g_y[(size_t)Mtot * Cn];
__device__ float g_ctx[BHn * Dn * Dn];
__device__ float g_ksum[BHn * Dn];

// ---------------------------------------------------------------------------
// helpers
// ---------------------------------------------------------------------------
__device__ __forceinline__ uint32_t smem_u32(const void* p) {
    uint32_t a;
    asm("{ .reg .u64 t; cvta.to.shared.u64 t, %1; cvt.u32.u64 %0, t; }"
        : "=r"(a) : "l"(p));
    return a;
}
__device__ __forceinline__ uint32_t f2tf32(float f) {
    uint32_t r;
    asm("cvt.rna.tf32.f32 %0, %1;" : "=r"(r) : "f"(f));
    return r;
}
#define CP_ASYNC16(dst, src) \
    asm volatile("cp.async.cg.shared.global [%0], [%1], 16;" :: "r"(dst), "l"(src))
#define CP_COMMIT() asm volatile("cp.async.commit_group;" ::: "memory")
#define CP_WAIT1()  asm volatile("cp.async.wait_group 1;" ::: "memory")
#define CP_WAIT0()  asm volatile("cp.async.wait_group 0;" ::: "memory")

__device__ __forceinline__ void mma_tf32(float* d, const uint32_t* a, const uint32_t* b) {
    asm volatile(
        "mma.sync.aligned.m16n8k8.row.col.f32.tf32.tf32.f32 "
        "{%0,%1,%2,%3}, {%4,%5,%6,%7}, {%8,%9}, {%0,%1,%2,%3};"
        : "+f"(d[0]), "+f"(d[1]), "+f"(d[2]), "+f"(d[3])
        : "r"(a[0]), "r"(a[1]), "r"(a[2]), "r"(a[3]), "r"(b[0]), "r"(b[1]));
}

// ---------------------------------------------------------------------------
// tf32 GEMM:  C[M,1024] = A[M,1024] @ W[1024,1024] + bias
// mode 0/1/2: A=x, C=g_q/g_k/g_v.  mode 3: A=g_y, C=out.
// Grid (8, 128), 256 threads = 8 warps (2 m x 4 n), warp tile 64x32.
// ---------------------------------------------------------------------------
constexpr int BM = 128, BN = 128, BK = 16;
constexpr int NCH = Cn / BK;            // 64
constexpr int AST = BK + 4;             // 20: row stride of As (floats)
constexpr int BST = BN + 8;             // 136: row stride of Bs (floats)

__global__ __launch_bounds__(256, 2)
void gemm_mma(const float* __restrict__ xA,
              const float* __restrict__ W,
              const float* __restrict__ bias,
              float* __restrict__ Cout,
              int mode)
{
    __shared__ float As[2][BM][AST];    // m-major, padded (stride 20)
    __shared__ float Bs[2][BK][BST];    // k-major, padded (stride 136)

    const int tid  = threadIdx.x;
    const int wid  = tid >> 5, lane = tid & 31;
    const int wm   = wid >> 2;          // 0..1  (64-row slab)
    const int wn   = wid & 3;           // 0..3  (32-col slab)
    const int bx   = blockIdx.x;        // N tile 0..7
    const int by   = blockIdx.y;        // M tile 0..127

    const float* A = (mode == 3) ? g_y : xA;
    float* C = (mode == 3) ? Cout : (mode == 0 ? g_q : (mode == 1 ? g_k : g_v));

    const float* Ap = A + (size_t)by * BM * Cn;
    const float* Wp = W + (size_t)bx * BN;

    // cp.async loader mapping (2 chunks each for A and B per thread per stage)
    const int am = tid >> 1;                 // 0..127 (row), 2 iters cover c4
    const int ac4 = (tid & 1) * 2;           // chunk col 0/2 (+1 in loop)
    const int bk_ = tid >> 4;                // 0..15 (row)
    const int bn4 = (tid & 15) * 2;          // 0..30 (+1 in loop)

    const uint32_t sAs = smem_u32(&As[0][0][0]);
    const uint32_t sBs = smem_u32(&Bs[0][0][0]);
    const uint32_t asBuf = BM * AST * 4;     // bytes per As buffer
    const uint32_t bsBuf = BK * BST * 4;

    auto load_stage = [&](int i, int buf) {
        const int k0 = i * BK;
#pragma unroll
        for (int c = 0; c < 2; c++) {
            const int cc = ac4 + c;          // 0..3
            CP_ASYNC16(sAs + buf * asBuf + (uint32_t)(am * AST + cc * 4) * 4,
                       Ap + (size_t)am * Cn + k0 + cc * 4);
        }
#pragma unroll
        for (int c = 0; c < 2; c++) {
            const int nn = bn4 + c;          // 0..31
            CP_ASYNC16(sBs + buf * bsBuf + (uint32_t)(bk_ * BST + nn * 4) * 4,
                       Wp + (size_t)(k0 + bk_) * Cn + nn * 4);
        }
        CP_COMMIT();
    };

    float acc[4][4][4];
#pragma unroll
    for (int i = 0; i < 4; i++)
#pragma unroll
        for (int j = 0; j < 4; j++)
#pragma unroll
            for (int r = 0; r < 4; r++) acc[i][j][r] = 0.f;

    load_stage(0, 0);

    const int lr = lane >> 2;     // 0..7
    const int lc = lane & 3;      // 0..3

    for (int i = 0; i < NCH; i++) {
        const int buf = i & 1;
        if (i + 1 < NCH) { load_stage(i + 1, buf ^ 1); CP_WAIT1(); }
        else             { CP_WAIT0(); }
        __syncthreads();

#pragma unroll
        for (int ks = 0; ks < 2; ks++) {
            const int k = ks * 8;
            uint32_t af[4][4];
#pragma unroll
            for (int mi = 0; mi < 4; mi++) {
                const int r = wm * 64 + mi * 16 + lr;
                af[mi][0] = f2tf32(As[buf][r][k + lc]);
                af[mi][1] = f2tf32(As[buf][r + 8][k + lc]);
                af[mi][2] = f2tf32(As[buf][r][k + lc + 4]);
                af[mi][3] = f2tf32(As[buf][r + 8][k + lc + 4]);
            }
            uint32_t bf[4][2];
#pragma unroll
            for (int ni = 0; ni < 4; ni++) {
                const int nn = wn * 32 + ni * 8 + lr;
                bf[ni][0] = f2tf32(Bs[buf][k + lc][nn]);
                bf[ni][1] = f2tf32(Bs[buf][k + lc + 4][nn]);
            }
#pragma unroll
            for (int mi = 0; mi < 4; mi++)
#pragma unroll
                for (int ni = 0; ni < 4; ni++)
                    mma_tf32(acc[mi][ni], af[mi], bf[ni]);
        }
        __syncthreads();
    }

    // Epilogue: bias + store (float2 per half-tile row)
#pragma unroll
    for (int mi = 0; mi < 4; mi++) {
        const int r0 = by * BM + wm * 64 + mi * 16 + lr;
#pragma unroll
        for (int ni = 0; ni < 4; ni++) {
            const int col = bx * BN + wn * 32 + ni * 8 + lc * 2;
            const float b0 = __ldg(bias + col), b1 = __ldg(bias + col + 1);
            float2 v0 = make_float2(acc[mi][ni][0] + b0, acc[mi][ni][1] + b1);
            float2 v1 = make_float2(acc[mi][ni][2] + b0, acc[mi][ni][3] + b1);
            *(float2*)(C + (size_t)r0 * Cn + col) = v0;
            *(float2*)(C + (size_t)(r0 + 8) * Cn + col) = v1;
        }
    }
}

// ---------------------------------------------------------------------------
// Softmax over 64-element head segments of g_q then g_k (1 warp per segment).
// ---------------------------------------------------------------------------
__global__ __launch_bounds__(256)
void softmax64()
{
    constexpr int NSEG = Mtot * Hn;
    const int w = (blockIdx.x * blockDim.x + threadIdx.x) >> 5;
    const int lane = threadIdx.x & 31;
    if (w >= 2 * NSEG) return;
    float* s = (w < NSEG) ? (g_q + (size_t)w * 64)
                          : (g_k + (size_t)(w - NSEG) * 64);
    float v0 = s[lane], v1 = s[lane + 32];
    float m = fmaxf(v0, v1);
#pragma unroll
    for (int o = 16; o; o >>= 1) m = fmaxf(m, __shfl_xor_sync(0xFFFFFFFFu, m, o));
    v0 = __expf(v0 - m);
    v1 = __expf(v1 - m);
    float sum = v0 + v1;
#pragma unroll
    for (int o = 16; o; o >>= 1) sum += __shfl_xor_sync(0xFFFFFFFFu, sum, o);
    const float inv = 1.0f / sum;
    s[lane] = v0 * inv;
    s[lane + 32] = v1 * inv;
}

__global__ void zero_ctx()
{
    const int i = blockIdx.x * blockDim.x + threadIdx.x;
    if (i < BHn * Dn * Dn) g_ctx[i] = 0.f;
    if (i < BHn * Dn) g_ksum[i] = 0.f;
}

constexpr int TSPLIT = 8;
__global__ __launch_bounds__(256)
void ctx_kernel()
{
    const int bh = blockIdx.x;
    const int b = bh / Hn, h = bh % Hn;
    const int t0 = blockIdx.y * (Tn / TSPLIT);
    const int tid = threadIdx.x;

    __shared__ float ks[32][64];
    __shared__ float vs[32][64];

    const int dbase = (tid / 16) * 4;
    const int ebase = (tid % 16) * 4;

    float acc[4][4];
#pragma unroll
    for (int i = 0; i < 4; i++)
#pragma unroll
        for (int j = 0; j < 4; j++) acc[i][j] = 0.f;
    float ksumAcc = 0.f;

    const size_t rowbase = (size_t)b * Tn * Cn + (size_t)h * Dn;
    const int lt = tid / 8;
    const int ld = (tid % 8) * 8;

    for (int tc = 0; tc < Tn / TSPLIT; tc += 32) {
        const size_t off = rowbase + (size_t)(t0 + tc + lt) * Cn + ld;
        float4 k0 = *(const float4*)(g_k + off);
        float4 k1 = *(const float4*)(g_k + off + 4);
        float4 v0 = *(const float4*)(g_v + off);
        float4 v1 = *(const float4*)(g_v + off + 4);
        *(float4*)&ks[lt][ld] = k0;
        *(float4*)&ks[lt][ld + 4] = k1;
        *(float4*)&vs[lt][ld] = v0;
        *(float4*)&vs[lt][ld + 4] = v1;
        __syncthreads();

#pragma unroll 8
        for (int t = 0; t < 32; t++) {
            float kr[4], vr[4];
#pragma unroll
            for (int i = 0; i < 4; i++) kr[i] = ks[t][dbase + i];
#pragma unroll
            for (int j = 0; j < 4; j++) vr[j] = vs[t][ebase + j];
#pragma unroll
            for (int i = 0; i < 4; i++)
#pragma unroll
                for (int j = 0; j < 4; j++)
                    acc[i][j] += kr[i] * vr[j];
        }
        if (tid < 64) {
#pragma unroll 8
            for (int t = 0; t < 32; t++) ksumAcc += ks[t][tid];
        }
        __syncthreads();
    }

#pragma unroll
    for (int i = 0; i < 4; i++)
#pragma unroll
        for (int j = 0; j < 4; j++)
            atomicAdd(&g_ctx[bh * Dn * Dn + (dbase + i) * Dn + ebase + j], acc[i][j]);
    if (tid < 64) atomicAdd(&g_ksum[bh * Dn + tid], ksumAcc);
}

__global__ __launch_bounds__(256)
void y_kernel()
{
    const int bh = blockIdx.x;
    const int b = bh / Hn, h = bh % Hn;
    const int tid = threadIdx.x;
    const int w = tid >> 5, lane = tid & 31;

    __shared__ float ctx_s[64][65];
    __shared__ float ksum_s[64];
    __shared__ float qrow[8][64];

    for (int i = tid; i < Dn * Dn; i += 256)
        ctx_s[i / 64][i % 64] = g_ctx[bh * Dn * Dn + i];
    if (tid < 64) ksum_s[tid] = g_ksum[bh * Dn + tid];
    __syncthreads();

    const size_t rowbase = (size_t)b * Tn * Cn + (size_t)h * Dn;

    for (int t = blockIdx.y * 64 + w; t < blockIdx.y * 64 + 64; t += 8) {
        const float* qp = g_q + rowbase + (size_t)t * Cn;
        const float q0 = qp[lane], q1 = qp[lane + 32];
        qrow[w][lane] = q0;
        qrow[w][lane + 32] = q1;
        __syncwarp();

        float s = q0 * ksum_s[lane] + q1 * ksum_s[lane + 32];
#pragma unroll
        for (int o = 16; o; o >>= 1) s += __shfl_xor_sync(0xFFFFFFFFu, s, o);
        const float dinv = 1.0f / s;

        float a0 = 0.f, a1 = 0.f;
#pragma unroll
        for (int d = 0; d < 64; d++) {
            const float qd = qrow[w][d];
            a0 += qd * ctx_s[d][lane];
            a1 += qd * ctx_s[d][lane + 32];
        }
        float* yp = g_y + rowbase + (size_t)t * Cn;
        yp[lane] = a0 * dinv + q0;
        yp[lane + 32] = a1 * dinv + q1;
        __syncwarp();
    }
}

// ---------------------------------------------------------------------------
extern "C" void kernel_launch(void* const* d_in, const int* in_sizes, int n_in,
                              void* d_out, int out_size)
{
    const float* x  = (const float*)d_in[0];
    const float* Wq = (const float*)d_in[1];
    const float* bq = (const float*)d_in[2];
    const float* Wk = (const float*)d_in[3];
    const float* bk = (const float*)d_in[4];
    const float* Wv = (const float*)d_in[5];
    const float* bv = (const float*)d_in[6];
    const float* Wp = (const float*)d_in[7];
    const float* bp = (const float*)d_in[8];
    float* out = (float*)d_out;

    const dim3 gGemm(Cn / BN, Mtot / BM);   // (8, 128)
    gemm_mma<<<gGemm, 256>>>(x, Wq, bq, nullptr, 0);
    gemm_mma<<<gGemm, 256>>>(x, Wk, bk, nullptr, 1);
    gemm_mma<<<gGemm, 256>>>(x, Wv, bv, nullptr, 2);

    softmax64<<<(2 * Mtot * Hn) / 8, 256>>>();   // 65536 blocks

    zero_ctx<<<(BHn * Dn * Dn + 255) / 256, 256>>>();
    ctx_kernel<<<dim3(BHn, TSPLIT), 256>>>();
    y_kernel<<<dim3(BHn, Tn / 64), 256>>>();

    gemm_mma<<<gGemm, 256>>>(nullptr, Wp, bp, out, 3);
}

// round 5
// speedup vs baseline: 3.8471x; 1.5079x over previous
#include <cuda_runtime.h>
#include <cuda_fp16.h>
#include <cstdint>

// ===========================================================================
// LinearAttention — Round 5: fp16 mma.sync GEMMs (f32 accumulate).
// fp16 has the same 10 explicit mantissa bits as tf32 but 2x the MMA rate.
//   0. cvt: x -> g_xh (fp16); W{q,k,v,p} -> g_WhT (fp16, transposed [n][k])
//   1. q/k/v = x @ W + b     (m16n8k16 fp16 mma, 128x128x32 tiles, cp.async)
//   2. softmax over head dim (64) on q, k     (fp32)
//   3. ctx = k^T v per (b,h); ksum            (fp32)
//   4. y = (q @ ctx) * Dinv + q  -> g_yh fp16
//   5. out = y @ Wp + bp     (same fp16 GEMM)
// ===========================================================================

constexpr int Bn   = 4;
constexpr int Tn   = 4096;
constexpr int Mtot = Bn * Tn;       // 16384
constexpr int Cn   = 1024;
constexpr int Hn   = 16;
constexpr int Dn   = 64;
constexpr int BHn  = Bn * Hn;       // 64

__device__ float  g_q[(size_t)Mtot * Cn];
__device__ float  g_k[(size_t)Mtot * Cn];
__device__ float  g_v[(size_t)Mtot * Cn];
__device__ __half g_xh[(size_t)Mtot * Cn];
__device__ __half g_yh[(size_t)Mtot * Cn];
__device__ __half g_WhT[4 * (size_t)Cn * Cn];   // [mode][n][k]
__device__ float  g_ctx[BHn * Dn * Dn];
__device__ float  g_ksum[BHn * Dn];

// ---------------------------------------------------------------------------
__device__ __forceinline__ uint32_t smem_u32(const void* p) {
    uint32_t a;
    asm("{ .reg .u64 t; cvta.to.shared.u64 t, %1; cvt.u32.u64 %0, t; }"
        : "=r"(a) : "l"(p));
    return a;
}
#define CP_ASYNC16(dst, src) \
    asm volatile("cp.async.cg.shared.global [%0], [%1], 16;" :: "r"(dst), "l"(src))
#define CP_COMMIT() asm volatile("cp.async.commit_group;" ::: "memory")
#define CP_WAIT1()  asm volatile("cp.async.wait_group 1;" ::: "memory")
#define CP_WAIT0()  asm volatile("cp.async.wait_group 0;" ::: "memory")

__device__ __forceinline__ void mma_f16(float* d, const uint32_t* a, const uint32_t* b) {
    asm volatile(
        "mma.sync.aligned.m16n8k16.row.col.f32.f16.f16.f32 "
        "{%0,%1,%2,%3}, {%4,%5,%6,%7}, {%8,%9}, {%0,%1,%2,%3};"
        : "+f"(d[0]), "+f"(d[1]), "+f"(d[2]), "+f"(d[3])
        : "r"(a[0]), "r"(a[1]), "r"(a[2]), "r"(a[3]), "r"(b[0]), "r"(b[1]));
}

// ---------------------------------------------------------------------------
// Conversion kernels
// ---------------------------------------------------------------------------
__global__ __launch_bounds__(256)
void cvt_x(const float* __restrict__ x)
{
    const int idx = blockIdx.x * 256 + threadIdx.x;       // 4 floats each
    const float4 v = ((const float4*)x)[idx];
    __half2 h0 = __floats2half2_rn(v.x, v.y);
    __half2 h1 = __floats2half2_rn(v.z, v.w);
    uint2 o;
    o.x = *(const uint32_t*)&h0;
    o.y = *(const uint32_t*)&h1;
    *(uint2*)(g_xh + (size_t)idx * 4) = o;
}

// dst[mode][n][k] = (half) W[k][n]
__global__ __launch_bounds__(256)
void cvt_wT(const float* __restrict__ src, int mode)
{
    __shared__ float tile[32][33];
    __half* dst = g_WhT + (size_t)mode * Cn * Cn;
    const int x = blockIdx.x * 32 + threadIdx.x;
    const int y = blockIdx.y * 32 + threadIdx.y;
#pragma unroll
    for (int j = 0; j < 32; j += 8)
        tile[threadIdx.y + j][threadIdx.x] = src[(size_t)(y + j) * Cn + x];
    __syncthreads();
    const int x2 = blockIdx.y * 32 + threadIdx.x;   // k index
    const int y2 = blockIdx.x * 32 + threadIdx.y;   // n index
#pragma unroll
    for (int j = 0; j < 32; j += 8)
        dst[(size_t)(y2 + j) * Cn + x2] = __float2half(tile[threadIdx.x][threadIdx.y + j]);
}

// ---------------------------------------------------------------------------
// fp16 GEMM:  C[M,1024] = A[M,1024] @ W[1024,1024] + bias   (C fp32)
// mode 0/1/2: A=g_xh, C=g_q/g_k/g_v.  mode 3: A=g_yh, C=out.
// Grid (8, 128), 256 threads = 8 warps (2 m x 4 n), warp tile 64x32.
// ---------------------------------------------------------------------------
constexpr int BM = 128, BN = 128, BK = 32;
constexpr int NCH = Cn / BK;            // 32
constexpr int HST = 40;                 // half-stride per row (20 words: conflict-free)

__global__ __launch_bounds__(256, 2)
void gemm_h(const float* __restrict__ bias,
            float* __restrict__ Cout,
            int mode)
{
    __shared__ __align__(16) __half As[2][BM][HST];
    __shared__ __align__(16) __half Bs[2][BN][HST];   // [n][k]

    const int tid  = threadIdx.x;
    const int wid  = tid >> 5, lane = tid & 31;
    const int wm   = wid >> 2;          // 0..1
    const int wn   = wid & 3;           // 0..3
    const int bx   = blockIdx.x;        // N tile 0..7
    const int by   = blockIdx.y;        // M tile 0..127

    const __half* A = (mode == 3) ? g_yh : g_xh;
    const __half* Bt = g_WhT + (size_t)mode * Cn * Cn;
    float* C = (mode == 3) ? Cout : (mode == 0 ? g_q : (mode == 1 ? g_k : g_v));

    const __half* Ap = A + (size_t)by * BM * Cn;
    const __half* Bp = Bt + (size_t)bx * BN * Cn;

    const uint32_t sAs = smem_u32(&As[0][0][0]);
    const uint32_t sBs = smem_u32(&Bs[0][0][0]);
    const uint32_t bufB = BM * HST * 2;          // bytes per buffer (10240)

    auto load_stage = [&](int i, int buf) {
        const int k0 = i * BK;
#pragma unroll
        for (int c = 0; c < 2; c++) {
            const int id = tid + c * 256;        // 0..511
            const int r = id >> 2, ch = id & 3;  // row, 8-half chunk
            CP_ASYNC16(sAs + buf * bufB + (uint32_t)(r * (HST * 2) + ch * 16),
                       Ap + (size_t)r * Cn + k0 + ch * 8);
        }
#pragma unroll
        for (int c = 0; c < 2; c++) {
            const int id = tid + c * 256;
            const int r = id >> 2, ch = id & 3;
            CP_ASYNC16(sBs + buf * bufB + (uint32_t)(r * (HST * 2) + ch * 16),
                       Bp + (size_t)r * Cn + k0 + ch * 8);
        }
        CP_COMMIT();
    };

    float acc[4][4][4];
#pragma unroll
    for (int i = 0; i < 4; i++)
#pragma unroll
        for (int j = 0; j < 4; j++)
#pragma unroll
            for (int r = 0; r < 4; r++) acc[i][j][r] = 0.f;

    load_stage(0, 0);

    const int lr = lane >> 2;     // 0..7 (group)
    const int lc = lane & 3;      // 0..3 (thread in group)

    for (int i = 0; i < NCH; i++) {
        const int buf = i & 1;
        if (i + 1 < NCH) { load_stage(i + 1, buf ^ 1); CP_WAIT1(); }
        else             { CP_WAIT0(); }
        __syncthreads();

#pragma unroll
        for (int ks = 0; ks < 2; ks++) {
            const int k = ks * 16;
            uint32_t af[4][4];
#pragma unroll
            for (int mi = 0; mi < 4; mi++) {
                const int r = wm * 64 + mi * 16 + lr;
                af[mi][0] = *(const uint32_t*)&As[buf][r][k + lc * 2];
                af[mi][1] = *(const uint32_t*)&As[buf][r + 8][k + lc * 2];
                af[mi][2] = *(const uint32_t*)&As[buf][r][k + lc * 2 + 8];
                af[mi][3] = *(const uint32_t*)&As[buf][r + 8][k + lc * 2 + 8];
            }
            uint32_t bf[4][2];
#pragma unroll
            for (int ni = 0; ni < 4; ni++) {
                const int nn = wn * 32 + ni * 8 + lr;
                bf[ni][0] = *(const uint32_t*)&Bs[buf][nn][k + lc * 2];
                bf[ni][1] = *(const uint32_t*)&Bs[buf][nn][k + lc * 2 + 8];
            }
#pragma unroll
            for (int mi = 0; mi < 4; mi++)
#pragma unroll
                for (int ni = 0; ni < 4; ni++)
                    mma_f16(acc[mi][ni], af[mi], bf[ni]);
        }
        __syncthreads();
    }

    // Epilogue: bias + fp32 store
#pragma unroll
    for (int mi = 0; mi < 4; mi++) {
        const int r0 = by * BM + wm * 64 + mi * 16 + lr;
#pragma unroll
        for (int ni = 0; ni < 4; ni++) {
            const int col = bx * BN + wn * 32 + ni * 8 + lc * 2;
            const float b0 = __ldg(bias + col), b1 = __ldg(bias + col + 1);
            float2 v0 = make_float2(acc[mi][ni][0] + b0, acc[mi][ni][1] + b1);
            float2 v1 = make_float2(acc[mi][ni][2] + b0, acc[mi][ni][3] + b1);
            *(float2*)(C + (size_t)r0 * Cn + col) = v0;
            *(float2*)(C + (size_t)(r0 + 8) * Cn + col) = v1;
        }
    }
}

// ---------------------------------------------------------------------------
// Softmax over 64-element head segments of g_q then g_k (1 warp per segment).
// ---------------------------------------------------------------------------
__global__ __launch_bounds__(256)
void softmax64()
{
    constexpr int NSEG = Mtot * Hn;
    const int w = (blockIdx.x * blockDim.x + threadIdx.x) >> 5;
    const int lane = threadIdx.x & 31;
    if (w >= 2 * NSEG) return;
    float* s = (w < NSEG) ? (g_q + (size_t)w * 64)
                          : (g_k + (size_t)(w - NSEG) * 64);
    float v0 = s[lane], v1 = s[lane + 32];
    float m = fmaxf(v0, v1);
#pragma unroll
    for (int o = 16; o; o >>= 1) m = fmaxf(m, __shfl_xor_sync(0xFFFFFFFFu, m, o));
    v0 = __expf(v0 - m);
    v1 = __expf(v1 - m);
    float sum = v0 + v1;
#pragma unroll
    for (int o = 16; o; o >>= 1) sum += __shfl_xor_sync(0xFFFFFFFFu, sum, o);
    const float inv = 1.0f / sum;
    s[lane] = v0 * inv;
    s[lane + 32] = v1 * inv;
}

__global__ void zero_ctx()
{
    const int i = blockIdx.x * blockDim.x + threadIdx.x;
    if (i < BHn * Dn * Dn) g_ctx[i] = 0.f;
    if (i < BHn * Dn) g_ksum[i] = 0.f;
}

constexpr int TSPLIT = 8;
__global__ __launch_bounds__(256)
void ctx_kernel()
{
    const int bh = blockIdx.x;
    const int b = bh / Hn, h = bh % Hn;
    const int t0 = blockIdx.y * (Tn / TSPLIT);
    const int tid = threadIdx.x;

    __shared__ float ks[32][64];
    __shared__ float vs[32][64];

    const int dbase = (tid / 16) * 4;
    const int ebase = (tid % 16) * 4;

    float acc[4][4];
#pragma unroll
    for (int i = 0; i < 4; i++)
#pragma unroll
        for (int j = 0; j < 4; j++) acc[i][j] = 0.f;
    float ksumAcc = 0.f;

    const size_t rowbase = (size_t)b * Tn * Cn + (size_t)h * Dn;
    const int lt = tid / 8;
    const int ld = (tid % 8) * 8;

    for (int tc = 0; tc < Tn / TSPLIT; tc += 32) {
        const size_t off = rowbase + (size_t)(t0 + tc + lt) * Cn + ld;
        float4 k0 = *(const float4*)(g_k + off);
        float4 k1 = *(const float4*)(g_k + off + 4);
        float4 v0 = *(const float4*)(g_v + off);
        float4 v1 = *(const float4*)(g_v + off + 4);
        *(float4*)&ks[lt][ld] = k0;
        *(float4*)&ks[lt][ld + 4] = k1;
        *(float4*)&vs[lt][ld] = v0;
        *(float4*)&vs[lt][ld + 4] = v1;
        __syncthreads();

#pragma unroll 8
        for (int t = 0; t < 32; t++) {
            float kr[4], vr[4];
#pragma unroll
            for (int i = 0; i < 4; i++) kr[i] = ks[t][dbase + i];
#pragma unroll
            for (int j = 0; j < 4; j++) vr[j] = vs[t][ebase + j];
#pragma unroll
            for (int i = 0; i < 4; i++)
#pragma unroll
                for (int j = 0; j < 4; j++)
                    acc[i][j] += kr[i] * vr[j];
        }
        if (tid < 64) {
#pragma unroll 8
            for (int t = 0; t < 32; t++) ksumAcc += ks[t][tid];
        }
        __syncthreads();
    }

#pragma unroll
    for (int i = 0; i < 4; i++)
#pragma unroll
        for (int j = 0; j < 4; j++)
            atomicAdd(&g_ctx[bh * Dn * Dn + (dbase + i) * Dn + ebase + j], acc[i][j]);
    if (tid < 64) atomicAdd(&g_ksum[bh * Dn + tid], ksumAcc);
}

// y -> g_yh (fp16) for the out-projection GEMM
__global__ __launch_bounds__(256)
void y_kernel()
{
    const int bh = blockIdx.x;
    const int b = bh / Hn, h = bh % Hn;
    const int tid = threadIdx.x;
    const int w = tid >> 5, lane = tid & 31;

    __shared__ float ctx_s[64][65];
    __shared__ float ksum_s[64];
    __shared__ float qrow[8][64];

    for (int i = tid; i < Dn * Dn; i += 256)
        ctx_s[i / 64][i % 64] = g_ctx[bh * Dn * Dn + i];
    if (tid < 64) ksum_s[tid] = g_ksum[bh * Dn + tid];
    __syncthreads();

    const size_t rowbase = (size_t)b * Tn * Cn + (size_t)h * Dn;

    for (int t = blockIdx.y * 64 + w; t < blockIdx.y * 64 + 64; t += 8) {
        const float* qp = g_q + rowbase + (size_t)t * Cn;
        const float q0 = qp[lane], q1 = qp[lane + 32];
        qrow[w][lane] = q0;
        qrow[w][lane + 32] = q1;
        __syncwarp();

        float s = q0 * ksum_s[lane] + q1 * ksum_s[lane + 32];
#pragma unroll
        for (int o = 16; o; o >>= 1) s += __shfl_xor_sync(0xFFFFFFFFu, s, o);
        const float dinv = 1.0f / s;

        float a0 = 0.f, a1 = 0.f;
#pragma unroll
        for (int d = 0; d < 64; d++) {
            const float qd = qrow[w][d];
            a0 += qd * ctx_s[d][lane];
            a1 += qd * ctx_s[d][lane + 32];
        }
        __half* yp = g_yh + rowbase + (size_t)t * Cn;
        yp[lane] = __float2half(a0 * dinv + q0);
        yp[lane + 32] = __float2half(a1 * dinv + q1);
        __syncwarp();
    }
}

// ---------------------------------------------------------------------------
extern "C" void kernel_launch(void* const* d_in, const int* in_sizes, int n_in,
                              void* d_out, int out_size)
{
    const float* x  = (const float*)d_in[0];
    const float* Wq = (const float*)d_in[1];
    const float* bq = (const float*)d_in[2];
    const float* Wk = (const float*)d_in[3];
    const float* bk = (const float*)d_in[4];
    const float* Wv = (const float*)d_in[5];
    const float* bv = (const float*)d_in[6];
    const float* Wp = (const float*)d_in[7];
    const float* bp = (const float*)d_in[8];
    float* out = (float*)d_out;

    // conversions
    cvt_x<<<(Mtot * Cn / 4) / 256, 256>>>(x);          // 16384 blocks
    const dim3 gT(Cn / 32, Cn / 32);
    cvt_wT<<<gT, dim3(32, 8)>>>(Wq, 0);
    cvt_wT<<<gT, dim3(32, 8)>>>(Wk, 1);
    cvt_wT<<<gT, dim3(32, 8)>>>(Wv, 2);
    cvt_wT<<<gT, dim3(32, 8)>>>(Wp, 3);

    const dim3 gGemm(Cn / BN, Mtot / BM);   // (8, 128)
    gemm_h<<<gGemm, 256>>>(bq, nullptr, 0);
    gemm_h<<<gGemm, 256>>>(bk, nullptr, 1);
    gemm_h<<<gGemm, 256>>>(bv, nullptr, 2);

    softmax64<<<(2 * Mtot * Hn) / 8, 256>>>();

    zero_ctx<<<(BHn * Dn * Dn + 255) / 256, 256>>>();
    ctx_kernel<<<dim3(BHn, TSPLIT), 256>>>();
    y_kernel<<<dim3(BHn, Tn / 64), 256>>>();

    gemm_h<<<gGemm, 256>>>(bp, out, 3);
}

// round 6
// speedup vs baseline: 4.0012x; 1.0401x over previous
#include <cuda_runtime.h>
#include <cuda_fp16.h>
#include <cstdint>

// ===========================================================================
// LinearAttention — Round 6:
//   - softmax fused into q/k GEMM epilogue (standalone softmax pass removed)
//   - k,v stored fp16 (q stays f32); ctx reads fp16
//   - 3-stage cp.async pipeline in the fp16 mma GEMM
// Pipeline:
//   0. cvt: x -> g_xh fp16; W{q,k,v,p} -> g_WhT fp16 transposed [n][k]
//   1. q = softmax(x@Wq+b) f32 | k = softmax(x@Wk+b) fp16 | v = x@Wv+b fp16
//   2. ctx = k^T v per (b,h); ksum
//   3. y = (q @ ctx) * Dinv + q  -> g_yh fp16
//   4. out = y @ Wp + bp (f32)
// ===========================================================================

constexpr int Bn   = 4;
constexpr int Tn   = 4096;
constexpr int Mtot = Bn * Tn;       // 16384
constexpr int Cn   = 1024;
constexpr int Hn   = 16;
constexpr int Dn   = 64;
constexpr int BHn  = Bn * Hn;       // 64

__device__ float  g_q[(size_t)Mtot * Cn];
__device__ __half g_kh[(size_t)Mtot * Cn];
__device__ __half g_vh[(size_t)Mtot * Cn];
__device__ __half g_xh[(size_t)Mtot * Cn];
__device__ __half g_yh[(size_t)Mtot * Cn];
__device__ __half g_WhT[4 * (size_t)Cn * Cn];   // [mode][n][k]
__device__ float  g_ctx[BHn * Dn * Dn];
__device__ float  g_ksum[BHn * Dn];

// ---------------------------------------------------------------------------
__device__ __forceinline__ uint32_t smem_u32(const void* p) {
    uint32_t a;
    asm("{ .reg .u64 t; cvta.to.shared.u64 t, %1; cvt.u32.u64 %0, t; }"
        : "=r"(a) : "l"(p));
    return a;
}
#define CP_ASYNC16(dst, src) \
    asm volatile("cp.async.cg.shared.global [%0], [%1], 16;" :: "r"(dst), "l"(src))
#define CP_COMMIT() asm volatile("cp.async.commit_group;" ::: "memory")
#define CP_WAIT2()  asm volatile("cp.async.wait_group 2;" ::: "memory")
#define CP_WAIT1()  asm volatile("cp.async.wait_group 1;" ::: "memory")
#define CP_WAIT0()  asm volatile("cp.async.wait_group 0;" ::: "memory")

__device__ __forceinline__ void mma_f16(float* d, const uint32_t* a, const uint32_t* b) {
    asm volatile(
        "mma.sync.aligned.m16n8k16.row.col.f32.f16.f16.f32 "
        "{%0,%1,%2,%3}, {%4,%5,%6,%7}, {%8,%9}, {%0,%1,%2,%3};"
        : "+f"(d[0]), "+f"(d[1]), "+f"(d[2]), "+f"(d[3])
        : "r"(a[0]), "r"(a[1]), "r"(a[2]), "r"(a[3]), "r"(b[0]), "r"(b[1]));
}

// ---------------------------------------------------------------------------
// Conversion kernels
// ---------------------------------------------------------------------------
__global__ __launch_bounds__(256)
void cvt_x(const float* __restrict__ x)
{
    const int idx = blockIdx.x * 256 + threadIdx.x;       // 4 floats each
    const float4 v = ((const float4*)x)[idx];
    __half2 h0 = __floats2half2_rn(v.x, v.y);
    __half2 h1 = __floats2half2_rn(v.z, v.w);
    uint2 o;
    o.x = *(const uint32_t*)&h0;
    o.y = *(const uint32_t*)&h1;
    *(uint2*)(g_xh + (size_t)idx * 4) = o;
}

// dst[mode][n][k] = (half) W[k][n]
__global__ __launch_bounds__(256)
void cvt_wT(const float* __restrict__ src, int mode)
{
    __shared__ float tile[32][33];
    __half* dst = g_WhT + (size_t)mode * Cn * Cn;
    const int x = blockIdx.x * 32 + threadIdx.x;
    const int y = blockIdx.y * 32 + threadIdx.y;
#pragma unroll
    for (int j = 0; j < 32; j += 8)
        tile[threadIdx.y + j][threadIdx.x] = src[(size_t)(y + j) * Cn + x];
    __syncthreads();
    const int x2 = blockIdx.y * 32 + threadIdx.x;   // k index
    const int y2 = blockIdx.x * 32 + threadIdx.y;   // n index
#pragma unroll
    for (int j = 0; j < 32; j += 8)
        dst[(size_t)(y2 + j) * Cn + x2] = __float2half(tile[threadIdx.x][threadIdx.y + j]);
}

// ---------------------------------------------------------------------------
// fp16 GEMM + fused epilogue.
// mode 0: q = softmax(x@Wq+b) -> g_q (f32)
// mode 1: k = softmax(x@Wk+b) -> g_kh (fp16)
// mode 2: v = x@Wv+b          -> g_vh (fp16)
// mode 3: out = y@Wp+b        -> Cout (f32)
// Grid (8, 128), 256 threads = 8 warps (2 m x 4 n), warp tile 64x32.
// ---------------------------------------------------------------------------
constexpr int BM = 128, BN = 128, BK = 32;
constexpr int NCH = Cn / BK;            // 32
constexpr int HST = 40;                 // half-stride per SMEM row
constexpr int NSTAGE = 3;
constexpr int STG = 132;                // f32 stage stride
constexpr int AB_BYTES = NSTAGE * BM * HST * 2;       // per array (30720)
constexpr int DSM_BYTES = BM * STG * 4;               // stage 67584 (> 2*AB_BYTES)

__global__ __launch_bounds__(256, 2)
void gemm_h(const float* __restrict__ bias,
            float* __restrict__ Cout,
            int mode)
{
    extern __shared__ __align__(16) char dsm[];
    __half* As = (__half*)dsm;                 // [NSTAGE][BM][HST]
    __half* Bs = (__half*)(dsm + AB_BYTES);    // [NSTAGE][BN][HST]
    float*  stage = (float*)dsm;               // [128][STG] (aliases As/Bs)

    const int tid  = threadIdx.x;
    const int wid  = tid >> 5, lane = tid & 31;
    const int wm   = wid >> 2;          // 0..1
    const int wn   = wid & 3;           // 0..3
    const int bx   = blockIdx.x;        // N tile 0..7
    const int by   = blockIdx.y;        // M tile 0..127

    const __half* A = (mode == 3) ? g_yh : g_xh;
    const __half* Bt = g_WhT + (size_t)mode * Cn * Cn;

    const __half* Ap = A + (size_t)by * BM * Cn;
    const __half* Bp = Bt + (size_t)bx * BN * Cn;

    const uint32_t sAs = smem_u32(As);
    const uint32_t sBs = smem_u32(Bs);
    const uint32_t bufB = BM * HST * 2;          // bytes per buffer (10240)

    const int ldr = tid >> 2, ldc = tid & 3;     // 0..63 rows x 4 chunks? no:
    // id covers 512 = 2 iters of 256: r = id>>2 (0..127), ch = id&3

    auto load_stage = [&](int i, int buf) {
        const int k0 = i * BK;
#pragma unroll
        for (int c = 0; c < 2; c++) {
            const int id = tid + c * 256;
            const int r = id >> 2, ch = id & 3;
            CP_ASYNC16(sAs + buf * bufB + (uint32_t)(r * (HST * 2) + ch * 16),
                       Ap + (size_t)r * Cn + k0 + ch * 8);
        }
#pragma unroll
        for (int c = 0; c < 2; c++) {
            const int id = tid + c * 256;
            const int r = id >> 2, ch = id & 3;
            CP_ASYNC16(sBs + buf * bufB + (uint32_t)(r * (HST * 2) + ch * 16),
                       Bp + (size_t)r * Cn + k0 + ch * 8);
        }
        CP_COMMIT();
    };

    float acc[4][4][4];
#pragma unroll
    for (int i = 0; i < 4; i++)
#pragma unroll
        for (int j = 0; j < 4; j++)
#pragma unroll
            for (int r = 0; r < 4; r++) acc[i][j][r] = 0.f;

    load_stage(0, 0);
    load_stage(1, 1);

    const int lr = lane >> 2;     // 0..7
    const int lc = lane & 3;      // 0..3

    for (int i = 0; i < NCH; i++) {
        const int buf = i % NSTAGE;
        if (i + 2 < NCH)      { load_stage(i + 2, (i + 2) % NSTAGE); CP_WAIT2(); }
        else if (i + 1 < NCH) { CP_WAIT1(); }
        else                  { CP_WAIT0(); }
        __syncthreads();

#pragma unroll
        for (int ks = 0; ks < 2; ks++) {
            const int k = ks * 16;
            uint32_t af[4][4];
#pragma unroll
            for (int mi = 0; mi < 4; mi++) {
                const int r = wm * 64 + mi * 16 + lr;
                const __half* a0 = As + buf * BM * HST + r * HST + k + lc * 2;
                const __half* a1 = As + buf * BM * HST + (r + 8) * HST + k + lc * 2;
                af[mi][0] = *(const uint32_t*)a0;
                af[mi][1] = *(const uint32_t*)a1;
                af[mi][2] = *(const uint32_t*)(a0 + 8);
                af[mi][3] = *(const uint32_t*)(a1 + 8);
            }
            uint32_t bf[4][2];
#pragma unroll
            for (int ni = 0; ni < 4; ni++) {
                const int nn = wn * 32 + ni * 8 + lr;
                const __half* b0 = Bs + buf * BM * HST + nn * HST + k + lc * 2;
                bf[ni][0] = *(const uint32_t*)b0;
                bf[ni][1] = *(const uint32_t*)(b0 + 8);
            }
#pragma unroll
            for (int mi = 0; mi < 4; mi++)
#pragma unroll
                for (int ni = 0; ni < 4; ni++)
                    mma_f16(acc[mi][ni], af[mi], bf[ni]);
        }
        __syncthreads();
    }

    if (mode == 3) {
        // plain f32 epilogue
#pragma unroll
        for (int mi = 0; mi < 4; mi++) {
            const int r0 = by * BM + wm * 64 + mi * 16 + lr;
#pragma unroll
            for (int ni = 0; ni < 4; ni++) {
                const int col = bx * BN + wn * 32 + ni * 8 + lc * 2;
                const float b0 = __ldg(bias + col), b1 = __ldg(bias + col + 1);
                float2 v0 = make_float2(acc[mi][ni][0] + b0, acc[mi][ni][1] + b1);
                float2 v1 = make_float2(acc[mi][ni][2] + b0, acc[mi][ni][3] + b1);
                *(float2*)(Cout + (size_t)r0 * Cn + col) = v0;
                *(float2*)(Cout + (size_t)(r0 + 8) * Cn + col) = v1;
            }
        }
        return;
    }
    if (mode == 2) {
        // v: fp16 store, no softmax
#pragma unroll
        for (int mi = 0; mi < 4; mi++) {
            const int r0 = by * BM + wm * 64 + mi * 16 + lr;
#pragma unroll
            for (int ni = 0; ni < 4; ni++) {
                const int col = bx * BN + wn * 32 + ni * 8 + lc * 2;
                const float b0 = __ldg(bias + col), b1 = __ldg(bias + col + 1);
                __half2 h0 = __floats2half2_rn(acc[mi][ni][0] + b0, acc[mi][ni][1] + b1);
                __half2 h1 = __floats2half2_rn(acc[mi][ni][2] + b0, acc[mi][ni][3] + b1);
                *(__half2*)(g_vh + (size_t)r0 * Cn + col) = h0;
                *(__half2*)(g_vh + (size_t)(r0 + 8) * Cn + col) = h1;
            }
        }
        return;
    }

    // modes 0/1: stage tile + per-head softmax (2 heads of 64 cols in this tile)
#pragma unroll
    for (int mi = 0; mi < 4; mi++) {
        const int r = wm * 64 + mi * 16 + lr;
#pragma unroll
        for (int ni = 0; ni < 4; ni++) {
            const int col = wn * 32 + ni * 8 + lc * 2;
            const float b0 = __ldg(bias + bx * BN + col);
            const float b1 = __ldg(bias + bx * BN + col + 1);
            stage[r * STG + col]           = acc[mi][ni][0] + b0;
            stage[r * STG + col + 1]       = acc[mi][ni][1] + b1;
            stage[(r + 8) * STG + col]     = acc[mi][ni][2] + b0;
            stage[(r + 8) * STG + col + 1] = acc[mi][ni][3] + b1;
        }
    }
    __syncthreads();

    // warp w handles rows w*16 .. w*16+15; lane l owns cols 4l..4l+3.
    // head0 = lanes 0..15 (cols 0..63), head1 = lanes 16..31 — xor offsets <16
    // never cross the boundary.
#pragma unroll 4
    for (int rr = 0; rr < 16; rr++) {
        const int row = wid * 16 + rr;
        float4 v4 = *(const float4*)&stage[row * STG + lane * 4];
        float m = fmaxf(fmaxf(v4.x, v4.y), fmaxf(v4.z, v4.w));
#pragma unroll
        for (int o = 8; o; o >>= 1) m = fmaxf(m, __shfl_xor_sync(0xFFFFFFFFu, m, o));
        v4.x = __expf(v4.x - m);
        v4.y = __expf(v4.y - m);
        v4.z = __expf(v4.z - m);
        v4.w = __expf(v4.w - m);
        float s = v4.x + v4.y + v4.z + v4.w;
#pragma unroll
        for (int o = 8; o; o >>= 1) s += __shfl_xor_sync(0xFFFFFFFFu, s, o);
        const float inv = 1.0f / s;
        v4.x *= inv; v4.y *= inv; v4.z *= inv; v4.w *= inv;

        const size_t gbase = (size_t)(by * BM + row) * Cn + bx * BN + lane * 4;
        if (mode == 0) {
            *(float4*)(g_q + gbase) = v4;
        } else {
            __half2 h0 = __floats2half2_rn(v4.x, v4.y);
            __half2 h1 = __floats2half2_rn(v4.z, v4.w);
            uint2 o2;
            o2.x = *(const uint32_t*)&h0;
            o2.y = *(const uint32_t*)&h1;
            *(uint2*)(g_kh + gbase) = o2;
        }
    }
}

// ---------------------------------------------------------------------------
__global__ void zero_ctx()
{
    const int i = blockIdx.x * blockDim.x + threadIdx.x;
    if (i < BHn * Dn * Dn) g_ctx[i] = 0.f;
    if (i < BHn * Dn) g_ksum[i] = 0.f;
}

// ctx[d][e] = sum_t k[t,d] v[t,e]; ksum[d] = sum_t k[t,d]   (k,v fp16 in)
constexpr int TSPLIT = 8;
__global__ __launch_bounds__(256)
void ctx_kernel()
{
    const int bh = blockIdx.x;
    const int b = bh / Hn, h = bh % Hn;
    const int t0 = blockIdx.y * (Tn / TSPLIT);
    const int tid = threadIdx.x;

    __shared__ float ks[32][64];
    __shared__ float vs[32][64];

    const int dbase = (tid / 16) * 4;
    const int ebase = (tid % 16) * 4;

    float acc[4][4];
#pragma unroll
    for (int i = 0; i < 4; i++)
#pragma unroll
        for (int j = 0; j < 4; j++) acc[i][j] = 0.f;
    float ksumAcc = 0.f;

    const size_t rowbase = (size_t)b * Tn * Cn + (size_t)h * Dn;
    const int lt = tid / 8;            // token 0..31
    const int ld = (tid % 8) * 8;      // d 0,8..56

    for (int tc = 0; tc < Tn / TSPLIT; tc += 32) {
        const size_t off = rowbase + (size_t)(t0 + tc + lt) * Cn + ld;
        uint4 kraw = *(const uint4*)(g_kh + off);   // 8 halves
        uint4 vraw = *(const uint4*)(g_vh + off);
        const __half2* kh = (const __half2*)&kraw;
        const __half2* vh = (const __half2*)&vraw;
#pragma unroll
        for (int c = 0; c < 4; c++) {
            float2 kf = __half22float2(kh[c]);
            float2 vf = __half22float2(vh[c]);
            ks[lt][ld + c * 2]     = kf.x;
            ks[lt][ld + c * 2 + 1] = kf.y;
            vs[lt][ld + c * 2]     = vf.x;
            vs[lt][ld + c * 2 + 1] = vf.y;
        }
        __syncthreads();

#pragma unroll 8
        for (int t = 0; t < 32; t++) {
            float kr[4], vr[4];
#pragma unroll
            for (int i = 0; i < 4; i++) kr[i] = ks[t][dbase + i];
#pragma unroll
            for (int j = 0; j < 4; j++) vr[j] = vs[t][ebase + j];
#pragma unroll
            for (int i = 0; i < 4; i++)
#pragma unroll
                for (int j = 0; j < 4; j++)
                    acc[i][j] += kr[i] * vr[j];
        }
        if (tid < 64) {
#pragma unroll 8
            for (int t = 0; t < 32; t++) ksumAcc += ks[t][tid];
        }
        __syncthreads();
    }

#pragma unroll
    for (int i = 0; i < 4; i++)
#pragma unroll
        for (int j = 0; j < 4; j++)
            atomicAdd(&g_ctx[bh * Dn * Dn + (dbase + i) * Dn + ebase + j], acc[i][j]);
    if (tid < 64) atomicAdd(&g_ksum[bh * Dn + tid], ksumAcc);
}

// y -> g_yh (fp16) for the out-projection GEMM
__global__ __launch_bounds__(256)
void y_kernel()
{
    const int bh = blockIdx.x;
    const int b = bh / Hn, h = bh % Hn;
    const int tid = threadIdx.x;
    const int w = tid >> 5, lane = tid & 31;

    __shared__ float ctx_s[64][65];
    __shared__ float ksum_s[64];
    __shared__ float qrow[8][64];

    for (int i = tid; i < Dn * Dn; i += 256)
        ctx_s[i / 64][i % 64] = g_ctx[bh * Dn * Dn + i];
    if (tid < 64) ksum_s[tid] = g_ksum[bh * Dn + tid];
    __syncthreads();

    const size_t rowbase = (size_t)b * Tn * Cn + (size_t)h * Dn;

    for (int t = blockIdx.y * 64 + w; t < blockIdx.y * 64 + 64; t += 8) {
        const float* qp = g_q + rowbase + (size_t)t * Cn;
        const float q0 = qp[lane], q1 = qp[lane + 32];
        qrow[w][lane] = q0;
        qrow[w][lane + 32] = q1;
        __syncwarp();

        float s = q0 * ksum_s[lane] + q1 * ksum_s[lane + 32];
#pragma unroll
        for (int o = 16; o; o >>= 1) s += __shfl_xor_sync(0xFFFFFFFFu, s, o);
        const float dinv = 1.0f / s;

        float a0 = 0.f, a1 = 0.f;
#pragma unroll
        for (int d = 0; d < 64; d++) {
            const float qd = qrow[w][d];
            a0 += qd * ctx_s[d][lane];
            a1 += qd * ctx_s[d][lane + 32];
        }
        __half* yp = g_yh + rowbase + (size_t)t * Cn;
        yp[lane] = __float2half(a0 * dinv + q0);
        yp[lane + 32] = __float2half(a1 * dinv + q1);
        __syncwarp();
    }
}

// ---------------------------------------------------------------------------
extern "C" void kernel_launch(void* const* d_in, const int* in_sizes, int n_in,
                              void* d_out, int out_size)
{
    const float* x  = (const float*)d_in[0];
    const float* Wq = (const float*)d_in[1];
    const float* bq = (const float*)d_in[2];
    const float* Wk = (const float*)d_in[3];
    const float* bk = (const float*)d_in[4];
    const float* Wv = (const float*)d_in[5];
    const float* bv = (const float*)d_in[6];
    const float* Wp = (const float*)d_in[7];
    const float* bp = (const float*)d_in[8];
    float* out = (float*)d_out;

    static bool attr_set = false;
    if (!attr_set) {
        cudaFuncSetAttribute(gemm_h, cudaFuncAttributeMaxDynamicSharedMemorySize, DSM_BYTES);
        attr_set = true;
    }

    // conversions
    cvt_x<<<(Mtot * Cn / 4) / 256, 256>>>(x);
    const dim3 gT(Cn / 32, Cn / 32);
    cvt_wT<<<gT, dim3(32, 8)>>>(Wq, 0);
    cvt_wT<<<gT, dim3(32, 8)>>>(Wk, 1);
    cvt_wT<<<gT, dim3(32, 8)>>>(Wv, 2);
    cvt_wT<<<gT, dim3(32, 8)>>>(Wp, 3);

    const dim3 gGemm(Cn / BN, Mtot / BM);   // (8, 128)
    gemm_h<<<gGemm, 256, DSM_BYTES>>>(bq, nullptr, 0);
    gemm_h<<<gGemm, 256, DSM_BYTES>>>(bk, nullptr, 1);
    gemm_h<<<gGemm, 256, DSM_BYTES>>>(bv, nullptr, 2);

    zero_ctx<<<(BHn * Dn * Dn + 255) / 256, 256>>>();
    ctx_kernel<<<dim3(BHn, TSPLIT), 256>>>();
    y_kernel<<<dim3(BHn, Tn / 64), 256>>>();

    gemm_h<<<gGemm, 256, DSM_BYTES>>>(bp, out, 3);
}